// round 15
// baseline (speedup 1.0000x reference)
#include <cuda_runtime.h>
#include <cuda_fp16.h>
#include <cstdint>
#include <math.h>

#define S_    64
#define I_    128
#define NO_   64
#define K_    64
#define D_    64
#define B_    64
#define TLEN_ 256
#define THR_  0.01f
#define NTHREADS 1024

#define WELEM  ((size_t)S_ * I_ * D_ * S_)
#define TOTAL4 (WELEM / 4)
#define PVSTRIDE 72   // halves per staged pv row: 144 B (16B-aligned, 4-way banks)

__device__ __half g_Th[WELEM];
__device__ __half g_Oh[WELEM];
__device__ float  g_pvt[I_ * S_ * D_];   // pv transposed fp32: [i][s][d]
__device__ __half g_pvh[I_ * S_ * D_];   // pv fp16: [i][d][s]
__device__ float  g_pgt[I_ * S_];        // push_gate transposed: [i][s]
__device__ float  g_ppt[I_ * S_];        // pop_gate transposed:  [i][s]

__global__ __launch_bounds__(256)
void cvt_kernel(const float* __restrict__ Ts, const float* __restrict__ Os) {
    size_t i = (size_t)blockIdx.x * blockDim.x + threadIdx.x;
    if (i >= TOTAL4) return;
    float4 a = ((const float4*)Ts)[i];
    float4 b = ((const float4*)Os)[i];
    __half2 a0 = __floats2half2_rn(a.x, a.y);
    __half2 a1 = __floats2half2_rn(a.z, a.w);
    __half2 b0 = __floats2half2_rn(b.x, b.y);
    __half2 b1 = __floats2half2_rn(b.z, b.w);
    uint2 ua, ub;
    ua.x = *(unsigned*)&a0; ua.y = *(unsigned*)&a1;
    ub.x = *(unsigned*)&b0; ub.y = *(unsigned*)&b1;
    ((uint2*)g_Th)[i] = ua;
    ((uint2*)g_Oh)[i] = ub;
}

__global__ __launch_bounds__(256)
void tr_kernel(const float* __restrict__ pg, const float* __restrict__ pp,
               const float* __restrict__ pv) {
    int idx = blockIdx.x * blockDim.x + threadIdx.x;
    if (idx < I_ * S_ * D_) {
        int d = idx & 63;
        int s = (idx >> 6) & 63;
        int i = idx >> 12;
        g_pvt[idx] = pv[(s * I_ + i) * D_ + d];
        int s2 = idx & 63;
        int d2 = (idx >> 6) & 63;
        int i2 = idx >> 12;
        g_pvh[idx] = __float2half(pv[(s2 * I_ + i2) * D_ + d2]);
    }
    if (idx < I_ * S_) {
        int s = idx & 63;
        int i = idx >> 6;
        g_pgt[idx] = pg[s * I_ + i];
        g_ppt[idx] = pp[s * I_ + i];
    }
}

// ---------- helpers ----------
__device__ __forceinline__ unsigned int s2u(const void* p) {
    unsigned int a;
    asm("{ .reg .u64 t; cvta.to.shared.u64 t, %1; cvt.u32.u64 %0, t; }" : "=r"(a) : "l"(p));
    return a;
}
__device__ __forceinline__ unsigned int ctarank() {
    unsigned int r; asm("mov.u32 %0, %%cluster_ctarank;" : "=r"(r)); return r;
}
__device__ __forceinline__ float tanh_fast(float x) {
    float y; asm("tanh.approx.f32 %0, %1;" : "=f"(y) : "f"(x)); return y;
}
__device__ __forceinline__ void st_rel_flag(unsigned int a, int v) {
    asm volatile("st.release.cluster.shared::cta.b32 [%0], %1;" :: "r"(a), "r"(v) : "memory");
}
__device__ __forceinline__ int ld_acq_remote(unsigned int laddr, unsigned int peer) {
    unsigned int ra; int v;
    asm("mapa.shared::cluster.u32 %0, %1, %2;" : "=r"(ra) : "r"(laddr), "r"(peer));
    asm volatile("ld.acquire.cluster.shared::cluster.b32 %0, [%1];" : "=r"(v) : "r"(ra) : "memory");
    return v;
}
__device__ __forceinline__ unsigned int ld_remote_u32(unsigned int laddr, unsigned int peer) {
    unsigned int ra, v;
    asm("mapa.shared::cluster.u32 %0, %1, %2;" : "=r"(ra) : "r"(laddr), "r"(peer));
    asm volatile("ld.shared::cluster.b32 %0, [%1];" : "=r"(v) : "r"(ra) : "memory");
    return v;
}
__device__ __forceinline__ void cp_async16(unsigned int dst, const void* src) {
    asm volatile("cp.async.cg.shared.global [%0], [%1], 16;" :: "r"(dst), "l"(src));
}
__device__ __forceinline__ void cp_commit() {
    asm volatile("cp.async.commit_group;" ::: "memory");
}
__device__ __forceinline__ void cp_wait0() {
    asm volatile("cp.async.wait_group 0;" ::: "memory");
}
__device__ __forceinline__ void pf_l2(const void* p) {
    asm volatile("prefetch.global.L2 [%0];" :: "l"(p));
}

// in-place softmax over 64 values: 8 per lane across an 8-lane group
__device__ __forceinline__ void softmax8(float* a) {
    float m = a[0];
    #pragma unroll
    for (int j = 1; j < 8; j++) m = fmaxf(m, a[j]);
    #pragma unroll
    for (int o = 4; o > 0; o >>= 1) m = fmaxf(m, __shfl_xor_sync(0xffffffffu, m, o, 8));
    float s = 0.f;
    #pragma unroll
    for (int j = 0; j < 8; j++) { a[j] = __expf(a[j] - m); s += a[j]; }
    #pragma unroll
    for (int o = 4; o > 0; o >>= 1) s += __shfl_xor_sync(0xffffffffu, s, o, 8);
    float inv = 1.0f / s;
    #pragma unroll
    for (int j = 0; j < 8; j++) a[j] *= inv;
}

// 16-aligned arrays first; odd-sized int arrays LAST (R11 lesson).
struct __align__(16) Smem {
    float    content[2][K_ * D_];            // 32 KB
    float    part[32 * 64];                  // 8 KB
    float    trace_state[TLEN_ + 1][S_];     // 65792 B
    unsigned trace_top[TLEN_ + 1][D_];       // 65792 B
    __half   pvst[64 * PVSTRIDE];            // 9216 B  cp.async stage: pv[sym1] rows padded
    float    gst[128];                       // 512 B   cp.async stage: pg row | pp row
    float    pb[2][K_];                      // 512 B
    float    pv2[2][D_];                     // 512 B
    __half   sh[S_];                         // 128 B
    float    scal[8];                        // 32 B
    float    tstate_l[S_];                   // 256 B
    unsigned ttop_l[D_];                     // 256 B
    int      flags[TLEN_ + 1];               // 1028 B (scalar only)
    int      seq_s[TLEN_ + 1];               // 1028 B (scalar only)
};

// dual-row contraction (fp16 slices, half2 weights tt), post-softmax in fa/fb
__device__ __forceinline__ void contract2(const uint4* __restrict__ A4,
                                          const uint4* __restrict__ B4,
                                          const unsigned int* __restrict__ tt,
                                          int lane, float* fa, float* fb)
{
    const int lr = lane >> 3;
    #pragma unroll
    for (int j = 0; j < 8; j++) { fa[j] = 0.f; fb[j] = 0.f; }
    const __half2 hz = __float2half2_rn(0.f);
    #pragma unroll
    for (int chunk = 0; chunk < 2; chunk++) {
        __half2 hA[4] = {hz, hz, hz, hz};
        __half2 hB[4] = {hz, hz, hz, hz};
        #pragma unroll
        for (int i = 0; i < 8; i++) {
            const int ii = chunk * 8 + i;
            unsigned int tb = tt[ii * 4 + lr];
            const __half2 td2 = *(__half2*)&tb;
            uint4 v = A4[ii * 32 + lane];
            hA[0] = __hfma2(td2, *(__half2*)&v.x, hA[0]);
            hA[1] = __hfma2(td2, *(__half2*)&v.y, hA[1]);
            hA[2] = __hfma2(td2, *(__half2*)&v.z, hA[2]);
            hA[3] = __hfma2(td2, *(__half2*)&v.w, hA[3]);
            uint4 u = B4[ii * 32 + lane];
            hB[0] = __hfma2(td2, *(__half2*)&u.x, hB[0]);
            hB[1] = __hfma2(td2, *(__half2*)&u.y, hB[1]);
            hB[2] = __hfma2(td2, *(__half2*)&u.z, hB[2]);
            hB[3] = __hfma2(td2, *(__half2*)&u.w, hB[3]);
        }
        #pragma unroll
        for (int c = 0; c < 4; c++) {
            float2 f = __half22float2(hA[c]);
            fa[2 * c] += f.x; fa[2 * c + 1] += f.y;
            f = __half22float2(hB[c]);
            fb[2 * c] += f.x; fb[2 * c + 1] += f.y;
        }
    }
    #pragma unroll
    for (int j = 0; j < 8; j++) {
        fa[j] += __shfl_xor_sync(0xffffffffu, fa[j], 8);
        fa[j] += __shfl_xor_sync(0xffffffffu, fa[j], 16);
        fb[j] += __shfl_xor_sync(0xffffffffu, fb[j], 8);
        fb[j] += __shfl_xor_sync(0xffffffffu, fb[j], 16);
    }
    softmax8(fa);
    softmax8(fb);
}

__global__ __launch_bounds__(NTHREADS, 1) __cluster_dims__(2, 1, 1)
void fpt_kernel(const int*   __restrict__ seq,
                const float* __restrict__ initl,
                float*       __restrict__ out)
{
    extern __shared__ char smem_raw[];
    Smem* sm = (Smem*)smem_raw;

    const int tid  = threadIdx.x;
    const int wid  = tid >> 5;
    const int lane = tid & 31;
    const int lc   = lane & 7;
    const int lr   = lane >> 3;
    const unsigned int rank = ctarank();
    const int b    = blockIdx.x >> 1;

    // ---- init (both ranks)
    if (tid < S_) sm->part[tid] = initl[tid];
    for (int e = tid; e <= TLEN_; e += NTHREADS) {
        sm->seq_s[e] = (e < TLEN_) ? seq[b * TLEN_ + e] : 0;
        sm->flags[e] = 0;
    }
    for (int e = tid; e < K_ * D_; e += NTHREADS) sm->content[0][e] = 0.f;
    if (tid < K_) { sm->pb[0][tid] = (tid == 0) ? 1.f : 0.f; sm->pb[1][tid] = 0.f; }
    if (tid < D_) sm->trace_top[0][tid] = 0u;
    __syncthreads();
    if (tid == 0) {
        float m = -1e30f;
        for (int i = 0; i < S_; i++) m = fmaxf(m, sm->part[i]);
        float ssum = 0.f;
        for (int i = 0; i < S_; i++) { float e = expf(sm->part[i] - m); sm->part[64 + i] = e; ssum += e; }
        sm->scal[2] = ssum;
    }
    __syncthreads();
    if (tid < S_) sm->trace_state[0][tid] = sm->part[64 + tid] / sm->scal[2];
    __syncthreads();

    // prologue (rank 0): gates(0), pushv(0)
    if (rank == 0) {
        const int sym0 = sm->seq_s[0];
        if (wid == 2) {
            float a = g_pgt[sym0 * 64 + lane] * sm->trace_state[0][lane]
                    + g_pgt[sym0 * 64 + 32 + lane] * sm->trace_state[0][lane + 32];
            #pragma unroll
            for (int o = 16; o > 0; o >>= 1) a += __shfl_xor_sync(0xffffffffu, a, o);
            if (lane == 0) sm->scal[0] = 1.f / (1.f + __expf(-a));
        } else if (wid == 3) {
            float a = g_ppt[sym0 * 64 + lane] * sm->trace_state[0][lane]
                    + g_ppt[sym0 * 64 + 32 + lane] * sm->trace_state[0][lane + 32];
            #pragma unroll
            for (int o = 16; o > 0; o >>= 1) a += __shfl_xor_sync(0xffffffffu, a, o);
            if (lane == 0) sm->scal[1] = 1.f / (1.f + __expf(-a));
        } else if (wid >= 6 && wid < 10) {
            const int d  = (wid - 6) * 16 + (lane & 15);
            const int sb = (lane >> 4) * 32;
            float acc = 0.f;
            #pragma unroll 8
            for (int j = 0; j < 32; j++)
                acc += sm->trace_state[0][sb + j] * g_pvt[sym0 * 4096 + (sb + j) * 64 + d];
            acc += __shfl_xor_sync(0xffffffffu, acc, 16);
            if ((lane >> 4) == 0) sm->pv2[0][d] = tanh_fast(acc);
        }
        __syncthreads();
    }

    asm volatile("barrier.cluster.arrive.aligned;" ::: "memory");
    asm volatile("barrier.cluster.wait.aligned;" ::: "memory");

    const unsigned int flags_u = s2u(&sm->flags[0]);
    const unsigned int pvst_u  = s2u(&sm->pvst[0]);
    const unsigned int gst_u   = s2u(&sm->gst[0]);

    if (rank == 0) {
        // ===================== recurrence CTA =====================
        int cb = 0;

        for (int t = 0; t < TLEN_; t++) {
            const int sym  = sm->seq_s[t];
            const int sym1 = sm->seq_s[t + 1];
            const int bp   = t & 1;

            if (tid == 0) st_rel_flag(flags_u + 4u * t, 1);   // publish step t

            // ---- A: pointer update in registers (all warps, redundant)
            const float pushs = sm->scal[0];
            const float pops  = sm->scal[1];
            const int i0 = lane * 2;
            float p0 = sm->pb[bp][i0], p1 = sm->pb[bp][i0 + 1];
            float dd = __shfl_down_sync(0xffffffffu, p0, 1);
            if (lane == 31) dd = 0.f;
            if (pops > THR_) {
                p0 = pops * p1 + (1.f - pops) * p0;
                p1 = pops * dd + (1.f - pops) * p1;
            }
            float uu = __shfl_up_sync(0xffffffffu, p1, 1);
            if (lane == 0) uu = 0.f;
            const float q0 = pushs * uu + (1.f - pushs) * p0;
            const float q1 = pushs * p0 + (1.f - pushs) * p1;
            const bool push = pushs > THR_;
            const float m0 = push ? q0 * (1.f - q0) : p0;
            const float m1 = push ? q1 * (1.f - q1) : p1;
            float cp = push ? (q0 * q0 + q1 * q1) : 0.f;
            #pragma unroll
            for (int o = 16; o > 0; o >>= 1) cp += __shfl_xor_sync(0xffffffffu, cp, o);
            if (wid == 31) {
                sm->pb[bp ^ 1][i0]     = push ? q0 : p0;
                sm->pb[bp ^ 1][i0 + 1] = push ? q1 : p1;
            }

            // ---- B: phase-2 T contraction (R10 form), then cp.async + L2 prefetch
            {
                const int r0 = wid * 2, r1 = r0 + 1;
                float fa[8], fb[8];
                contract2((const uint4*)(g_Th + (size_t)(r0 * I_ + sym) * 4096),
                          (const uint4*)(g_Th + (size_t)(r1 * I_ + sym) * 4096),
                          sm->trace_top[t], lane, fa, fb);
                const float s0 = sm->trace_state[t][r0];
                const float s1 = sm->trace_state[t][r1];
                if (lr == 0) {
                    float4 w;
                    w.x = s0 * fa[0] + s1 * fb[0]; w.y = s0 * fa[1] + s1 * fb[1];
                    w.z = s0 * fa[2] + s1 * fb[2]; w.w = s0 * fa[3] + s1 * fb[3];
                    *(float4*)&sm->part[wid * 64 + lc * 8] = w;
                    w.x = s0 * fa[4] + s1 * fb[4]; w.y = s0 * fa[5] + s1 * fb[5];
                    w.z = s0 * fa[6] + s1 * fb[6]; w.w = s0 * fa[7] + s1 * fb[7];
                    *(float4*)&sm->part[wid * 64 + lc * 8 + 4] = w;
                }

                // cp.async staging for D-region gates/pushv (after load burst; R7 lesson)
                if (tid < 64) {
                    const char* psrc = (const char*)(g_pvh + (size_t)sym1 * 4096) + tid * 128;
                    unsigned dstb = pvst_u + (unsigned)tid * (PVSTRIDE * 2);
                    #pragma unroll
                    for (int j = 0; j < 8; j++)
                        cp_async16(dstb + (unsigned)j * 16u, psrc + j * 16);
                    if (lane < 16) {
                        if (wid == 0)
                            cp_async16(gst_u + (unsigned)lane * 16u,
                                       (const char*)(g_pgt + sym1 * 64) + lane * 16);
                        else
                            cp_async16(gst_u + 256u + (unsigned)lane * 16u,
                                       (const char*)(g_ppt + sym1 * 64) + lane * 16);
                    }
                    cp_commit();
                }

                // L2 prefetch of step t+1's T slices (after all issue; pure overlap)
                const char* pfa = (const char*)(g_Th + (size_t)(r0 * I_ + sym1) * 4096);
                const char* pfb = (const char*)(g_Th + (size_t)(r1 * I_ + sym1) * 4096);
                pf_l2(pfa + lane * 128); pf_l2(pfa + 4096 + lane * 128);
                pf_l2(pfb + lane * 128); pf_l2(pfb + 4096 + lane * 128);
            }
            __syncthreads();   // B1

            // ---- D: reduce+gates+pushv || stack_top(t+1) || content update
            if (tid < 64) {
                // reduce
                float ns = 0.f;
                #pragma unroll
                for (int r = 0; r < 32; r++) ns += sm->part[r * 64 + tid];
                sm->trace_state[t + 1][tid] = ns;
                sm->sh[tid] = __float2half(ns);
                cp_wait0();
                asm volatile("bar.sync 4, 64;" ::: "memory");  // sh + staged copies visible
                // pushv(t+1): one d per lane (padded rows: 4-way banks, 16B aligned)
                {
                    const uint4* pr = (const uint4*)(sm->pvst + tid * PVSTRIDE);
                    const __half2* s2h = (const __half2*)sm->sh;
                    float a = 0.f;
                    #pragma unroll
                    for (int u = 0; u < 8; u++) {
                        uint4 v = pr[u];
                        __half2 h0 = __hmul2(s2h[u * 4 + 0], *(__half2*)&v.x);
                        __half2 h1 = __hmul2(s2h[u * 4 + 1], *(__half2*)&v.y);
                        __half2 h2 = __hmul2(s2h[u * 4 + 2], *(__half2*)&v.z);
                        __half2 h3 = __hmul2(s2h[u * 4 + 3], *(__half2*)&v.w);
                        float2 f0 = __half22float2(h0), f1 = __half22float2(h1);
                        float2 f2 = __half22float2(h2), f3 = __half22float2(h3);
                        a += (f0.x + f0.y) + (f1.x + f1.y) + (f2.x + f2.y) + (f3.x + f3.y);
                    }
                    sm->pv2[bp ^ 1][tid] = tanh_fast(a);
                }
                // gates(t+1): warp0 -> pg, warp1 -> pp (reads trace_state post-bar)
                {
                    const float* gr = sm->gst + wid * 64;
                    float a = gr[lane] * sm->trace_state[t + 1][lane]
                            + gr[lane + 32] * sm->trace_state[t + 1][lane + 32];
                    #pragma unroll
                    for (int o = 16; o > 0; o >>= 1) a += __shfl_xor_sync(0xffffffffu, a, o);
                    if (lane == 0) sm->scal[wid] = 1.f / (1.f + __expf(-a));
                }
            } else if (wid >= 2 && wid < 6) {
                const int d  = (wid - 2) * 16 + (lane & 15);
                const int kb = (lane >> 4) * 32;
                float acc = 0.f;
                #pragma unroll 8
                for (int j = 0; j < 32; j++) {
                    float mv = __shfl_sync(0xffffffffu, (j & 1) ? m1 : m0,
                                           (kb >> 1) + (j >> 1));
                    acc += mv * sm->content[cb][(kb + j) * 64 + d];
                }
                acc += __shfl_xor_sync(0xffffffffu, acc, 16);
                if ((lane >> 4) == 0) {
                    __half2 h = __float2half2_rn(acc + cp * sm->pv2[bp][d]);
                    sm->trace_top[t + 1][d] = *(unsigned int*)&h;
                }
            } else if (wid >= 16) {
                if (push) {
                    const int tidc = tid - 512;
                    const int kbase = tidc >> 6;      // warp-uniform
                    const float pvd = sm->pv2[bp][tidc & 63];
                    #pragma unroll
                    for (int i = 0; i < 8; i++) {
                        const int k = kbase + 8 * i;
                        float wk = __shfl_sync(0xffffffffu, (k & 1) ? q1 : q0, k >> 1);
                        const int e = tidc + 512 * i;
                        sm->content[cb ^ 1][e] =
                            sm->content[cb][e] * (1.f - wk) + pvd * wk;
                    }
                }
            }
            if (push) cb ^= 1;
            __syncthreads();   // B3 / loop top
        }
    } else {
        // ===================== output CTA (lagging consumer) =====================
        const int r0 = wid * 2, r1 = r0 + 1;
        const unsigned int peer = 0u;

        for (int t = 0; t < TLEN_; t++) {
            if (tid == 0) {
                while (ld_acq_remote(flags_u + 4u * t, peer) == 0) { }
            }
            __syncthreads();
            if (tid < 64) {
                unsigned int v = ld_remote_u32(s2u(&sm->trace_state[t][tid]), peer);
                sm->tstate_l[tid] = __uint_as_float(v);
            } else if (tid < 128) {
                sm->ttop_l[tid - 64] = ld_remote_u32(s2u(&sm->trace_top[t][tid - 64]), peer);
            }
            __syncthreads();

            const int sym = sm->seq_s[t];
            float fa[8], fb[8];
            contract2((const uint4*)(g_Oh + (size_t)(r0 * I_ + sym) * 4096),
                      (const uint4*)(g_Oh + (size_t)(r1 * I_ + sym) * 4096),
                      sm->ttop_l, lane, fa, fb);
            const float s0 = sm->tstate_l[r0];
            const float s1 = sm->tstate_l[r1];
            if (lr == 0) {
                float4 w;
                w.x = s0 * fa[0] + s1 * fb[0]; w.y = s0 * fa[1] + s1 * fb[1];
                w.z = s0 * fa[2] + s1 * fb[2]; w.w = s0 * fa[3] + s1 * fb[3];
                *(float4*)&sm->part[wid * 64 + lc * 8] = w;
                w.x = s0 * fa[4] + s1 * fb[4]; w.y = s0 * fa[5] + s1 * fb[5];
                w.z = s0 * fa[6] + s1 * fb[6]; w.w = s0 * fa[7] + s1 * fb[7];
                *(float4*)&sm->part[wid * 64 + lc * 8 + 4] = w;
            }
            __syncthreads();

            if (tid < 64) {
                float m = 0.f;
                #pragma unroll
                for (int r = 0; r < 32; r++) m += sm->part[r * 64 + tid];
                out[((size_t)b * TLEN_ + t) * NO_ + tid] = m;
            }
        }
    }

    asm volatile("barrier.cluster.arrive.aligned;" ::: "memory");
    asm volatile("barrier.cluster.wait.aligned;" ::: "memory");
}

extern "C" void kernel_launch(void* const* d_in, const int* in_sizes, int n_in,
                              void* d_out, int out_size)
{
    const int*   seq   = (const int*)  d_in[0];
    const float* Tt    = (const float*)d_in[1];
    const float* Ot    = (const float*)d_in[2];
    const float* pgate = (const float*)d_in[3];
    const float* pop   = (const float*)d_in[4];
    const float* pval  = (const float*)d_in[5];
    const float* initl = (const float*)d_in[6];
    float* out = (float*)d_out;

    cudaFuncSetAttribute(fpt_kernel, cudaFuncAttributeMaxDynamicSharedMemorySize,
                         (int)sizeof(Smem));

    cvt_kernel<<<(unsigned)((TOTAL4 + 255) / 256), 256>>>(Tt, Ot);
    tr_kernel<<<(I_ * S_ * D_ + 255) / 256, 256>>>(pgate, pop, pval);
    fpt_kernel<<<2 * B_, NTHREADS, sizeof(Smem)>>>(seq, initl, out);
}

// round 16
// speedup vs baseline: 1.0173x; 1.0173x over previous
#include <cuda_runtime.h>
#include <cuda_fp16.h>
#include <cstdint>
#include <math.h>

#define S_    64
#define I_    128
#define NO_   64
#define K_    64
#define D_    64
#define B_    64
#define TLEN_ 256
#define THR_  0.01f
#define NTHREADS 1024

#define WELEM  ((size_t)S_ * I_ * D_ * S_)
#define TOTAL4 (WELEM / 4)

__device__ __half g_Th[WELEM];
__device__ __half g_Oh[WELEM];
__device__ float  g_pvt[I_ * S_ * D_];   // pv transposed fp32: [i][s][d]
__device__ __half g_pvh[I_ * S_ * D_];   // pv fp16: [i][d][s]
__device__ float  g_pgt[I_ * S_];        // push_gate transposed: [i][s]
__device__ float  g_ppt[I_ * S_];        // pop_gate transposed:  [i][s]

__global__ __launch_bounds__(256)
void cvt_kernel(const float* __restrict__ Ts, const float* __restrict__ Os) {
    size_t i = (size_t)blockIdx.x * blockDim.x + threadIdx.x;
    if (i >= TOTAL4) return;
    float4 a = ((const float4*)Ts)[i];
    float4 b = ((const float4*)Os)[i];
    __half2 a0 = __floats2half2_rn(a.x, a.y);
    __half2 a1 = __floats2half2_rn(a.z, a.w);
    __half2 b0 = __floats2half2_rn(b.x, b.y);
    __half2 b1 = __floats2half2_rn(b.z, b.w);
    uint2 ua, ub;
    ua.x = *(unsigned*)&a0; ua.y = *(unsigned*)&a1;
    ub.x = *(unsigned*)&b0; ub.y = *(unsigned*)&b1;
    ((uint2*)g_Th)[i] = ua;
    ((uint2*)g_Oh)[i] = ub;
}

__global__ __launch_bounds__(256)
void tr_kernel(const float* __restrict__ pg, const float* __restrict__ pp,
               const float* __restrict__ pv) {
    int idx = blockIdx.x * blockDim.x + threadIdx.x;
    if (idx < I_ * S_ * D_) {
        int d = idx & 63;
        int s = (idx >> 6) & 63;
        int i = idx >> 12;
        g_pvt[idx] = pv[(s * I_ + i) * D_ + d];
        int s2 = idx & 63;
        int d2 = (idx >> 6) & 63;
        int i2 = idx >> 12;
        g_pvh[idx] = __float2half(pv[(s2 * I_ + i2) * D_ + d2]);
    }
    if (idx < I_ * S_) {
        int s = idx & 63;
        int i = idx >> 6;
        g_pgt[idx] = pg[s * I_ + i];
        g_ppt[idx] = pp[s * I_ + i];
    }
}

// ---------- helpers ----------
__device__ __forceinline__ unsigned int s2u(const void* p) {
    unsigned int a;
    asm("{ .reg .u64 t; cvta.to.shared.u64 t, %1; cvt.u32.u64 %0, t; }" : "=r"(a) : "l"(p));
    return a;
}
__device__ __forceinline__ unsigned int ctarank() {
    unsigned int r; asm("mov.u32 %0, %%cluster_ctarank;" : "=r"(r)); return r;
}
__device__ __forceinline__ float tanh_fast(float x) {
    float y; asm("tanh.approx.f32 %0, %1;" : "=f"(y) : "f"(x)); return y;
}
__device__ __forceinline__ void st_rel_flag(unsigned int a, int v) {
    asm volatile("st.release.cluster.shared::cta.b32 [%0], %1;" :: "r"(a), "r"(v) : "memory");
}
__device__ __forceinline__ int ld_acq_remote(unsigned int laddr, unsigned int peer) {
    unsigned int ra; int v;
    asm("mapa.shared::cluster.u32 %0, %1, %2;" : "=r"(ra) : "r"(laddr), "r"(peer));
    asm volatile("ld.acquire.cluster.shared::cluster.b32 %0, [%1];" : "=r"(v) : "r"(ra) : "memory");
    return v;
}
__device__ __forceinline__ unsigned int ld_remote_u32(unsigned int laddr, unsigned int peer) {
    unsigned int ra, v;
    asm("mapa.shared::cluster.u32 %0, %1, %2;" : "=r"(ra) : "r"(laddr), "r"(peer));
    asm volatile("ld.shared::cluster.b32 %0, [%1];" : "=r"(v) : "r"(ra) : "memory");
    return v;
}
__device__ __forceinline__ void cp_async16(unsigned int dst, const void* src) {
    asm volatile("cp.async.cg.shared.global [%0], [%1], 16;" :: "r"(dst), "l"(src));
}
__device__ __forceinline__ void cp_commit() {
    asm volatile("cp.async.commit_group;" ::: "memory");
}
__device__ __forceinline__ void cp_wait0() {
    asm volatile("cp.async.wait_group 0;" ::: "memory");
}
__device__ __forceinline__ void pf_l2(const void* p) {
    asm volatile("prefetch.global.L2 [%0];" :: "l"(p));
}

// in-place softmax over 64 values: 8 per lane across an 8-lane group
__device__ __forceinline__ void softmax8(float* a) {
    float m = a[0];
    #pragma unroll
    for (int j = 1; j < 8; j++) m = fmaxf(m, a[j]);
    #pragma unroll
    for (int o = 4; o > 0; o >>= 1) m = fmaxf(m, __shfl_xor_sync(0xffffffffu, m, o, 8));
    float s = 0.f;
    #pragma unroll
    for (int j = 0; j < 8; j++) { a[j] = __expf(a[j] - m); s += a[j]; }
    #pragma unroll
    for (int o = 4; o > 0; o >>= 1) s += __shfl_xor_sync(0xffffffffu, s, o, 8);
    float inv = 1.0f / s;
    #pragma unroll
    for (int j = 0; j < 8; j++) a[j] *= inv;
}

// 16-aligned arrays first; odd-sized int arrays LAST (R11 lesson).
struct __align__(16) Smem {
    float    content[2][K_ * D_];          // 32 KB
    float    part[32 * 64];                // 8 KB
    float    trace_state[TLEN_ + 1][S_];   // 65792 B
    unsigned trace_top[TLEN_ + 1][D_];     // 65792 B
    __half   pvst[64 * 64];                // 8 KB  cp.async stage: pv[sym1] [d][s]
    float    gst[128];                     // 512 B cp.async stage: pg row | pp row
    float    pb[2][K_];                    // 512 B
    float    pv2[2][D_];                   // 512 B
    __half   sh[S_];                       // 128 B
    float    scal[8];                      // 32 B
    float    tstate_l[S_];                 // 256 B
    unsigned ttop_l[D_];                   // 256 B
    int      flags[TLEN_ + 1];             // 1028 B (scalar only)
    int      seq_s[TLEN_ + 1];             // 1028 B (scalar only)
};

// dual-row contraction (fp16 slices, half2 weights tt), post-softmax in fa/fb
__device__ __forceinline__ void contract2(const uint4* __restrict__ A4,
                                          const uint4* __restrict__ B4,
                                          const unsigned int* __restrict__ tt,
                                          int lane, float* fa, float* fb)
{
    const int lr = lane >> 3;
    #pragma unroll
    for (int j = 0; j < 8; j++) { fa[j] = 0.f; fb[j] = 0.f; }
    const __half2 hz = __float2half2_rn(0.f);
    #pragma unroll
    for (int chunk = 0; chunk < 2; chunk++) {
        __half2 hA[4] = {hz, hz, hz, hz};
        __half2 hB[4] = {hz, hz, hz, hz};
        #pragma unroll
        for (int i = 0; i < 8; i++) {
            const int ii = chunk * 8 + i;
            unsigned int tb = tt[ii * 4 + lr];
            const __half2 td2 = *(__half2*)&tb;
            uint4 v = A4[ii * 32 + lane];
            hA[0] = __hfma2(td2, *(__half2*)&v.x, hA[0]);
            hA[1] = __hfma2(td2, *(__half2*)&v.y, hA[1]);
            hA[2] = __hfma2(td2, *(__half2*)&v.z, hA[2]);
            hA[3] = __hfma2(td2, *(__half2*)&v.w, hA[3]);
            uint4 u = B4[ii * 32 + lane];
            hB[0] = __hfma2(td2, *(__half2*)&u.x, hB[0]);
            hB[1] = __hfma2(td2, *(__half2*)&u.y, hB[1]);
            hB[2] = __hfma2(td2, *(__half2*)&u.z, hB[2]);
            hB[3] = __hfma2(td2, *(__half2*)&u.w, hB[3]);
        }
        #pragma unroll
        for (int c = 0; c < 4; c++) {
            float2 f = __half22float2(hA[c]);
            fa[2 * c] += f.x; fa[2 * c + 1] += f.y;
            f = __half22float2(hB[c]);
            fb[2 * c] += f.x; fb[2 * c + 1] += f.y;
        }
    }
    #pragma unroll
    for (int j = 0; j < 8; j++) {
        fa[j] += __shfl_xor_sync(0xffffffffu, fa[j], 8);
        fa[j] += __shfl_xor_sync(0xffffffffu, fa[j], 16);
        fb[j] += __shfl_xor_sync(0xffffffffu, fb[j], 8);
        fb[j] += __shfl_xor_sync(0xffffffffu, fb[j], 16);
    }
    softmax8(fa);
    softmax8(fb);
}

__global__ __launch_bounds__(NTHREADS, 1) __cluster_dims__(2, 1, 1)
void fpt_kernel(const int*   __restrict__ seq,
                const float* __restrict__ initl,
                float*       __restrict__ out)
{
    extern __shared__ char smem_raw[];
    Smem* sm = (Smem*)smem_raw;

    const int tid  = threadIdx.x;
    const int wid  = tid >> 5;
    const int lane = tid & 31;
    const int lc   = lane & 7;
    const int lr   = lane >> 3;
    const unsigned int rank = ctarank();
    const int b    = blockIdx.x >> 1;

    // ---- init (both ranks)
    if (tid < S_) sm->part[tid] = initl[tid];
    for (int e = tid; e <= TLEN_; e += NTHREADS) {
        sm->seq_s[e] = (e < TLEN_) ? seq[b * TLEN_ + e] : 0;
        sm->flags[e] = 0;
    }
    for (int e = tid; e < K_ * D_; e += NTHREADS) sm->content[0][e] = 0.f;
    if (tid < K_) { sm->pb[0][tid] = (tid == 0) ? 1.f : 0.f; sm->pb[1][tid] = 0.f; }
    if (tid < D_) sm->trace_top[0][tid] = 0u;
    __syncthreads();
    if (tid == 0) {
        float m = -1e30f;
        for (int i = 0; i < S_; i++) m = fmaxf(m, sm->part[i]);
        float ssum = 0.f;
        for (int i = 0; i < S_; i++) { float e = expf(sm->part[i] - m); sm->part[64 + i] = e; ssum += e; }
        sm->scal[2] = ssum;
    }
    __syncthreads();
    if (tid < S_) sm->trace_state[0][tid] = sm->part[64 + tid] / sm->scal[2];
    __syncthreads();

    // prologue (rank 0): gates(0), pushv(0)
    if (rank == 0) {
        const int sym0 = sm->seq_s[0];
        if (wid == 2) {
            float a = g_pgt[sym0 * 64 + lane] * sm->trace_state[0][lane]
                    + g_pgt[sym0 * 64 + 32 + lane] * sm->trace_state[0][lane + 32];
            #pragma unroll
            for (int o = 16; o > 0; o >>= 1) a += __shfl_xor_sync(0xffffffffu, a, o);
            if (lane == 0) sm->scal[0] = 1.f / (1.f + __expf(-a));
        } else if (wid == 3) {
            float a = g_ppt[sym0 * 64 + lane] * sm->trace_state[0][lane]
                    + g_ppt[sym0 * 64 + 32 + lane] * sm->trace_state[0][lane + 32];
            #pragma unroll
            for (int o = 16; o > 0; o >>= 1) a += __shfl_xor_sync(0xffffffffu, a, o);
            if (lane == 0) sm->scal[1] = 1.f / (1.f + __expf(-a));
        } else if (wid >= 6 && wid < 10) {
            const int d  = (wid - 6) * 16 + (lane & 15);
            const int sb = (lane >> 4) * 32;
            float acc = 0.f;
            #pragma unroll 8
            for (int j = 0; j < 32; j++)
                acc += sm->trace_state[0][sb + j] * g_pvt[sym0 * 4096 + (sb + j) * 64 + d];
            acc += __shfl_xor_sync(0xffffffffu, acc, 16);
            if ((lane >> 4) == 0) sm->pv2[0][d] = tanh_fast(acc);
        }
        __syncthreads();
    }

    asm volatile("barrier.cluster.arrive.aligned;" ::: "memory");
    asm volatile("barrier.cluster.wait.aligned;" ::: "memory");

    const unsigned int flags_u = s2u(&sm->flags[0]);
    const unsigned int pvst_u  = s2u(&sm->pvst[0]);
    const unsigned int gst_u   = s2u(&sm->gst[0]);

    if (rank == 0) {
        // ===================== recurrence CTA =====================
        int cb = 0;

        for (int t = 0; t < TLEN_; t++) {
            const int sym  = sm->seq_s[t];
            const int sym1 = sm->seq_s[t + 1];
            const int bp   = t & 1;

            if (tid == 0) st_rel_flag(flags_u + 4u * t, 1);   // publish step t

            // ---- cp.async preloads for the F region (operands depend only on sym1)
            if (wid == 6) {
                if (lane < 16)
                    cp_async16(gst_u + (unsigned)lane * 16u,
                               (const char*)(g_pgt + sym1 * 64) + lane * 16);
                cp_commit();
            } else if (wid == 7) {
                if (lane < 16)
                    cp_async16(gst_u + 256u + (unsigned)lane * 16u,
                               (const char*)(g_ppt + sym1 * 64) + lane * 16);
                cp_commit();
            } else if (wid >= 8 && wid < 12) {
                const int idx = (wid - 8) * 32 + lane;
                const char* base = (const char*)(g_pvh + (size_t)sym1 * 4096);
                #pragma unroll
                for (int c = 0; c < 4; c++)
                    cp_async16(pvst_u + (unsigned)(idx + c * 128) * 16u,
                               base + (size_t)(idx + c * 128) * 16);
                cp_commit();
            }

            // ---- A: pointer update in registers (all warps, redundant)
            const float pushs = sm->scal[0];
            const float pops  = sm->scal[1];
            const int i0 = lane * 2;
            float p0 = sm->pb[bp][i0], p1 = sm->pb[bp][i0 + 1];
            float dd = __shfl_down_sync(0xffffffffu, p0, 1);
            if (lane == 31) dd = 0.f;
            if (pops > THR_) {
                p0 = pops * p1 + (1.f - pops) * p0;
                p1 = pops * dd + (1.f - pops) * p1;
            }
            float uu = __shfl_up_sync(0xffffffffu, p1, 1);
            if (lane == 0) uu = 0.f;
            const float q0 = pushs * uu + (1.f - pushs) * p0;
            const float q1 = pushs * p0 + (1.f - pushs) * p1;
            const bool push = pushs > THR_;
            const float m0 = push ? q0 * (1.f - q0) : p0;
            const float m1 = push ? q1 * (1.f - q1) : p1;
            float cp = push ? (q0 * q0 + q1 * q1) : 0.f;
            #pragma unroll
            for (int o = 16; o > 0; o >>= 1) cp += __shfl_xor_sync(0xffffffffu, cp, o);
            if (wid == 31) {
                sm->pb[bp ^ 1][i0]     = push ? q0 : p0;
                sm->pb[bp ^ 1][i0 + 1] = push ? q1 : p1;
            }

            // ---- B: phase-2 T contraction (R10 form) + L2 prefetch of t+1 slices
            {
                const int r0 = wid * 2, r1 = r0 + 1;
                float fa[8], fb[8];
                contract2((const uint4*)(g_Th + (size_t)(r0 * I_ + sym) * 4096),
                          (const uint4*)(g_Th + (size_t)(r1 * I_ + sym) * 4096),
                          sm->trace_top[t], lane, fa, fb);
                const float s0 = sm->trace_state[t][r0];
                const float s1 = sm->trace_state[t][r1];
                if (lr == 0) {
                    float4 w;
                    w.x = s0 * fa[0] + s1 * fb[0]; w.y = s0 * fa[1] + s1 * fb[1];
                    w.z = s0 * fa[2] + s1 * fb[2]; w.w = s0 * fa[3] + s1 * fb[3];
                    *(float4*)&sm->part[wid * 64 + lc * 8] = w;
                    w.x = s0 * fa[4] + s1 * fb[4]; w.y = s0 * fa[5] + s1 * fb[5];
                    w.z = s0 * fa[6] + s1 * fb[6]; w.w = s0 * fa[7] + s1 * fb[7];
                    *(float4*)&sm->part[wid * 64 + lc * 8 + 4] = w;
                }
                // L2 prefetch of step t+1's T slices: issued AFTER this step's load
                // burst and part store (R7 lesson). Pure overlap of the serial tail.
                const char* pfa = (const char*)(g_Th + (size_t)(r0 * I_ + sym1) * 4096);
                const char* pfb = (const char*)(g_Th + (size_t)(r1 * I_ + sym1) * 4096);
                pf_l2(pfa + lane * 128); pf_l2(pfa + 4096 + lane * 128);
                pf_l2(pfb + lane * 128); pf_l2(pfb + 4096 + lane * 128);
            }
            __syncthreads();   // B1

            // ---- D: reduce || stack_top(t+1) || content update  (parallel)
            if (tid < 64) {
                float ns = 0.f;
                #pragma unroll
                for (int r = 0; r < 32; r++) ns += sm->part[r * 64 + tid];
                sm->trace_state[t + 1][tid] = ns;
                sm->sh[tid] = __float2half(ns);
            } else if (wid >= 2 && wid < 6) {
                const int d  = (wid - 2) * 16 + (lane & 15);
                const int kb = (lane >> 4) * 32;
                float acc = 0.f;
                #pragma unroll 8
                for (int j = 0; j < 32; j++) {
                    float mv = __shfl_sync(0xffffffffu, (j & 1) ? m1 : m0,
                                           (kb >> 1) + (j >> 1));
                    acc += mv * sm->content[cb][(kb + j) * 64 + d];
                }
                acc += __shfl_xor_sync(0xffffffffu, acc, 16);
                if ((lane >> 4) == 0) {
                    __half2 h = __float2half2_rn(acc + cp * sm->pv2[bp][d]);
                    sm->trace_top[t + 1][d] = *(unsigned int*)&h;
                }
            } else if (wid >= 16) {
                if (push) {
                    const int tidc = tid - 512;
                    const int kbase = tidc >> 6;      // warp-uniform
                    const float pvd = sm->pv2[bp][tidc & 63];
                    #pragma unroll
                    for (int i = 0; i < 8; i++) {
                        const int k = kbase + 8 * i;
                        float wk = __shfl_sync(0xffffffffu, (k & 1) ? q1 : q0, k >> 1);
                        const int e = tidc + 512 * i;
                        sm->content[cb ^ 1][e] =
                            sm->content[cb][e] * (1.f - wk) + pvd * wk;
                    }
                }
            }
            __syncthreads();   // B2

            // ---- F: gates(t+1) + pushv(t+1), operands already staged in smem
            if (wid == 6) {
                cp_wait0();
                float a = sm->gst[lane] * sm->trace_state[t + 1][lane]
                        + sm->gst[lane + 32] * sm->trace_state[t + 1][lane + 32];
                #pragma unroll
                for (int o = 16; o > 0; o >>= 1) a += __shfl_xor_sync(0xffffffffu, a, o);
                if (lane == 0) sm->scal[0] = 1.f / (1.f + __expf(-a));
            } else if (wid == 7) {
                cp_wait0();
                float a = sm->gst[64 + lane] * sm->trace_state[t + 1][lane]
                        + sm->gst[64 + lane + 32] * sm->trace_state[t + 1][lane + 32];
                #pragma unroll
                for (int o = 16; o > 0; o >>= 1) a += __shfl_xor_sync(0xffffffffu, a, o);
                if (lane == 0) sm->scal[1] = 1.f / (1.f + __expf(-a));
            } else if (wid >= 8 && wid < 12) {
                cp_wait0();
                const int d   = (wid - 8) * 16 + (lane >> 1);
                const int shh = lane & 1;
                const uint4* pr = (const uint4*)(sm->pvst + d * 64 + shh * 32);
                const __half2* s2h = (const __half2*)sm->sh + shh * 16;
                float a = 0.f;
                #pragma unroll
                for (int u = 0; u < 4; u++) {
                    uint4 v = pr[u];
                    __half2 h0 = __hmul2(s2h[u * 4 + 0], *(__half2*)&v.x);
                    __half2 h1 = __hmul2(s2h[u * 4 + 1], *(__half2*)&v.y);
                    __half2 h2 = __hmul2(s2h[u * 4 + 2], *(__half2*)&v.z);
                    __half2 h3 = __hmul2(s2h[u * 4 + 3], *(__half2*)&v.w);
                    float2 f0 = __half22float2(h0), f1 = __half22float2(h1);
                    float2 f2 = __half22float2(h2), f3 = __half22float2(h3);
                    a += (f0.x + f0.y) + (f1.x + f1.y) + (f2.x + f2.y) + (f3.x + f3.y);
                }
                a += __shfl_xor_sync(0xffffffffu, a, 1);
                sm->pv2[bp ^ 1][d] = tanh_fast(a);
            }
            if (push) cb ^= 1;
            __syncthreads();   // B3 / loop top
        }
    } else {
        // ===================== output CTA (lagging consumer) =====================
        const int r0 = wid * 2, r1 = r0 + 1;
        const unsigned int peer = 0u;

        for (int t = 0; t < TLEN_; t++) {
            if (tid == 0) {
                while (ld_acq_remote(flags_u + 4u * t, peer) == 0) { }
            }
            __syncthreads();
            if (tid < 64) {
                unsigned int v = ld_remote_u32(s2u(&sm->trace_state[t][tid]), peer);
                sm->tstate_l[tid] = __uint_as_float(v);
            } else if (tid < 128) {
                sm->ttop_l[tid - 64] = ld_remote_u32(s2u(&sm->trace_top[t][tid - 64]), peer);
            }
            __syncthreads();

            const int sym = sm->seq_s[t];
            float fa[8], fb[8];
            contract2((const uint4*)(g_Oh + (size_t)(r0 * I_ + sym) * 4096),
                      (const uint4*)(g_Oh + (size_t)(r1 * I_ + sym) * 4096),
                      sm->ttop_l, lane, fa, fb);
            const float s0 = sm->tstate_l[r0];
            const float s1 = sm->tstate_l[r1];
            if (lr == 0) {
                float4 w;
                w.x = s0 * fa[0] + s1 * fb[0]; w.y = s0 * fa[1] + s1 * fb[1];
                w.z = s0 * fa[2] + s1 * fb[2]; w.w = s0 * fa[3] + s1 * fb[3];
                *(float4*)&sm->part[wid * 64 + lc * 8] = w;
                w.x = s0 * fa[4] + s1 * fb[4]; w.y = s0 * fa[5] + s1 * fb[5];
                w.z = s0 * fa[6] + s1 * fb[6]; w.w = s0 * fa[7] + s1 * fb[7];
                *(float4*)&sm->part[wid * 64 + lc * 8 + 4] = w;
            }
            __syncthreads();

            if (tid < 64) {
                float m = 0.f;
                #pragma unroll
                for (int r = 0; r < 32; r++) m += sm->part[r * 64 + tid];
                out[((size_t)b * TLEN_ + t) * NO_ + tid] = m;
            }
        }
    }

    asm volatile("barrier.cluster.arrive.aligned;" ::: "memory");
    asm volatile("barrier.cluster.wait.aligned;" ::: "memory");
}

extern "C" void kernel_launch(void* const* d_in, const int* in_sizes, int n_in,
                              void* d_out, int out_size)
{
    const int*   seq   = (const int*)  d_in[0];
    const float* Tt    = (const float*)d_in[1];
    const float* Ot    = (const float*)d_in[2];
    const float* pgate = (const float*)d_in[3];
    const float* pop   = (const float*)d_in[4];
    const float* pval  = (const float*)d_in[5];
    const float* initl = (const float*)d_in[6];
    float* out = (float*)d_out;

    cudaFuncSetAttribute(fpt_kernel, cudaFuncAttributeMaxDynamicSharedMemorySize,
                         (int)sizeof(Smem));

    cvt_kernel<<<(unsigned)((TOTAL4 + 255) / 256), 256>>>(Tt, Ot);
    tr_kernel<<<(I_ * S_ * D_ + 255) / 256, 256>>>(pgate, pop, pval);
    fpt_kernel<<<2 * B_, NTHREADS, sizeof(Smem)>>>(seq, initl, out);
}

// round 17
// speedup vs baseline: 1.1031x; 1.0844x over previous
#include <cuda_runtime.h>
#include <cuda_fp16.h>
#include <cstdint>
#include <math.h>

#define S_    64
#define I_    128
#define NO_   64
#define K_    64
#define D_    64
#define B_    64
#define TLEN_ 256
#define THR_  0.01f
#define NTHREADS 1024

#define WELEM  ((size_t)S_ * I_ * D_ * S_)
#define TOTAL4 (WELEM / 4)

__device__ __half g_Th[WELEM];
__device__ __half g_Oh[WELEM];
__device__ float  g_pvt[I_ * S_ * D_];   // pv transposed fp32: [i][s][d]
__device__ __half g_pvh[I_ * S_ * D_];   // pv fp16: [i][d][s]
__device__ float  g_pgt[I_ * S_];        // push_gate transposed: [i][s]
__device__ float  g_ppt[I_ * S_];        // pop_gate transposed:  [i][s]

__global__ __launch_bounds__(256)
void cvt_kernel(const float* __restrict__ Ts, const float* __restrict__ Os) {
    size_t i = (size_t)blockIdx.x * blockDim.x + threadIdx.x;
    if (i >= TOTAL4) return;
    float4 a = ((const float4*)Ts)[i];
    float4 b = ((const float4*)Os)[i];
    __half2 a0 = __floats2half2_rn(a.x, a.y);
    __half2 a1 = __floats2half2_rn(a.z, a.w);
    __half2 b0 = __floats2half2_rn(b.x, b.y);
    __half2 b1 = __floats2half2_rn(b.z, b.w);
    uint2 ua, ub;
    ua.x = *(unsigned*)&a0; ua.y = *(unsigned*)&a1;
    ub.x = *(unsigned*)&b0; ub.y = *(unsigned*)&b1;
    ((uint2*)g_Th)[i] = ua;
    ((uint2*)g_Oh)[i] = ub;
}

__global__ __launch_bounds__(256)
void tr_kernel(const float* __restrict__ pg, const float* __restrict__ pp,
               const float* __restrict__ pv) {
    int idx = blockIdx.x * blockDim.x + threadIdx.x;
    if (idx < I_ * S_ * D_) {
        int d = idx & 63;
        int s = (idx >> 6) & 63;
        int i = idx >> 12;
        g_pvt[idx] = pv[(s * I_ + i) * D_ + d];
        int s2 = idx & 63;
        int d2 = (idx >> 6) & 63;
        int i2 = idx >> 12;
        g_pvh[idx] = __float2half(pv[(s2 * I_ + i2) * D_ + d2]);
    }
    if (idx < I_ * S_) {
        int s = idx & 63;
        int i = idx >> 6;
        g_pgt[idx] = pg[s * I_ + i];
        g_ppt[idx] = pp[s * I_ + i];
    }
}

// ---------- helpers ----------
__device__ __forceinline__ unsigned int s2u(const void* p) {
    unsigned int a;
    asm("{ .reg .u64 t; cvta.to.shared.u64 t, %1; cvt.u32.u64 %0, t; }" : "=r"(a) : "l"(p));
    return a;
}
__device__ __forceinline__ unsigned int ctarank() {
    unsigned int r; asm("mov.u32 %0, %%cluster_ctarank;" : "=r"(r)); return r;
}
__device__ __forceinline__ float tanh_fast(float x) {
    float y; asm("tanh.approx.f32 %0, %1;" : "=f"(y) : "f"(x)); return y;
}
__device__ __forceinline__ void st_rel_flag(unsigned int a, int v) {
    asm volatile("st.release.cluster.shared::cta.b32 [%0], %1;" :: "r"(a), "r"(v) : "memory");
}
__device__ __forceinline__ int ld_acq_remote(unsigned int laddr, unsigned int peer) {
    unsigned int ra; int v;
    asm("mapa.shared::cluster.u32 %0, %1, %2;" : "=r"(ra) : "r"(laddr), "r"(peer));
    asm volatile("ld.acquire.cluster.shared::cluster.b32 %0, [%1];" : "=r"(v) : "r"(ra) : "memory");
    return v;
}
__device__ __forceinline__ unsigned int ld_remote_u32(unsigned int laddr, unsigned int peer) {
    unsigned int ra, v;
    asm("mapa.shared::cluster.u32 %0, %1, %2;" : "=r"(ra) : "r"(laddr), "r"(peer));
    asm volatile("ld.shared::cluster.b32 %0, [%1];" : "=r"(v) : "r"(ra) : "memory");
    return v;
}
__device__ __forceinline__ void cp_async16(unsigned int dst, const void* src) {
    asm volatile("cp.async.cg.shared.global [%0], [%1], 16;" :: "r"(dst), "l"(src));
}
__device__ __forceinline__ void cp_commit() {
    asm volatile("cp.async.commit_group;" ::: "memory");
}
__device__ __forceinline__ void cp_wait0() {
    asm volatile("cp.async.wait_group 0;" ::: "memory");
}

// in-place softmax over 64 values: 8 per lane across an 8-lane group
__device__ __forceinline__ void softmax8(float* a) {
    float m = a[0];
    #pragma unroll
    for (int j = 1; j < 8; j++) m = fmaxf(m, a[j]);
    #pragma unroll
    for (int o = 4; o > 0; o >>= 1) m = fmaxf(m, __shfl_xor_sync(0xffffffffu, m, o, 8));
    float s = 0.f;
    #pragma unroll
    for (int j = 0; j < 8; j++) { a[j] = __expf(a[j] - m); s += a[j]; }
    #pragma unroll
    for (int o = 4; o > 0; o >>= 1) s += __shfl_xor_sync(0xffffffffu, s, o, 8);
    float inv = 1.0f / s;
    #pragma unroll
    for (int j = 0; j < 8; j++) a[j] *= inv;
}

// 16-aligned arrays first; odd-sized int arrays LAST (R11 lesson).
struct __align__(16) Smem {
    float    content[2][K_ * D_];          // 32 KB
    float    part[32 * 64];                // 8 KB
    float    trace_state[TLEN_ + 1][S_];   // 65792 B
    unsigned trace_top[TLEN_ + 1][D_];     // 65792 B
    __half   pvst[64 * 64];                // 8 KB  cp.async stage: pv[sym1] [d][s]
    float    gst[128];                     // 512 B cp.async stage: pg row | pp row
    float    pb[2][K_];                    // 512 B
    float    pv2[2][D_];                   // 512 B
    __half   sh[S_];                       // 128 B
    float    scal[8];                      // 32 B
    float    tstate_l[S_];                 // 256 B
    unsigned ttop_l[D_];                   // 256 B
    int      flags[TLEN_ + 1];             // 1028 B (scalar only)
    int      seq_s[TLEN_ + 1];             // 1028 B (scalar only)
};

// dual-row contraction (fp16 slices, half2 weights tt), post-softmax in fa/fb
__device__ __forceinline__ void contract2(const uint4* __restrict__ A4,
                                          const uint4* __restrict__ B4,
                                          const unsigned int* __restrict__ tt,
                                          int lane, float* fa, float* fb)
{
    const int lr = lane >> 3;
    #pragma unroll
    for (int j = 0; j < 8; j++) { fa[j] = 0.f; fb[j] = 0.f; }
    const __half2 hz = __float2half2_rn(0.f);
    #pragma unroll
    for (int chunk = 0; chunk < 2; chunk++) {
        __half2 hA[4] = {hz, hz, hz, hz};
        __half2 hB[4] = {hz, hz, hz, hz};
        #pragma unroll
        for (int i = 0; i < 8; i++) {
            const int ii = chunk * 8 + i;
            unsigned int tb = tt[ii * 4 + lr];
            const __half2 td2 = *(__half2*)&tb;
            uint4 v = A4[ii * 32 + lane];
            hA[0] = __hfma2(td2, *(__half2*)&v.x, hA[0]);
            hA[1] = __hfma2(td2, *(__half2*)&v.y, hA[1]);
            hA[2] = __hfma2(td2, *(__half2*)&v.z, hA[2]);
            hA[3] = __hfma2(td2, *(__half2*)&v.w, hA[3]);
            uint4 u = B4[ii * 32 + lane];
            hB[0] = __hfma2(td2, *(__half2*)&u.x, hB[0]);
            hB[1] = __hfma2(td2, *(__half2*)&u.y, hB[1]);
            hB[2] = __hfma2(td2, *(__half2*)&u.z, hB[2]);
            hB[3] = __hfma2(td2, *(__half2*)&u.w, hB[3]);
        }
        #pragma unroll
        for (int c = 0; c < 4; c++) {
            float2 f = __half22float2(hA[c]);
            fa[2 * c] += f.x; fa[2 * c + 1] += f.y;
            f = __half22float2(hB[c]);
            fb[2 * c] += f.x; fb[2 * c + 1] += f.y;
        }
    }
    #pragma unroll
    for (int j = 0; j < 8; j++) {
        fa[j] += __shfl_xor_sync(0xffffffffu, fa[j], 8);
        fa[j] += __shfl_xor_sync(0xffffffffu, fa[j], 16);
        fb[j] += __shfl_xor_sync(0xffffffffu, fb[j], 8);
        fb[j] += __shfl_xor_sync(0xffffffffu, fb[j], 16);
    }
    softmax8(fa);
    softmax8(fb);
}

__global__ __launch_bounds__(NTHREADS, 1) __cluster_dims__(2, 1, 1)
void fpt_kernel(const int*   __restrict__ seq,
                const float* __restrict__ initl,
                float*       __restrict__ out)
{
    extern __shared__ char smem_raw[];
    Smem* sm = (Smem*)smem_raw;

    const int tid  = threadIdx.x;
    const int wid  = tid >> 5;
    const int lane = tid & 31;
    const int lc   = lane & 7;
    const int lr   = lane >> 3;
    const unsigned int rank = ctarank();
    const int b    = blockIdx.x >> 1;

    // ---- init (both ranks)
    if (tid < S_) sm->part[tid] = initl[tid];
    for (int e = tid; e <= TLEN_; e += NTHREADS) {
        sm->seq_s[e] = (e < TLEN_) ? seq[b * TLEN_ + e] : 0;
        sm->flags[e] = 0;
    }
    for (int e = tid; e < K_ * D_; e += NTHREADS) sm->content[0][e] = 0.f;
    if (tid < K_) { sm->pb[0][tid] = (tid == 0) ? 1.f : 0.f; sm->pb[1][tid] = 0.f; }
    if (tid < D_) sm->trace_top[0][tid] = 0u;
    __syncthreads();
    if (tid == 0) {
        float m = -1e30f;
        for (int i = 0; i < S_; i++) m = fmaxf(m, sm->part[i]);
        float ssum = 0.f;
        for (int i = 0; i < S_; i++) { float e = expf(sm->part[i] - m); sm->part[64 + i] = e; ssum += e; }
        sm->scal[2] = ssum;
    }
    __syncthreads();
    if (tid < S_) sm->trace_state[0][tid] = sm->part[64 + tid] / sm->scal[2];
    __syncthreads();

    // prologue (rank 0): gates(0), pushv(0)
    if (rank == 0) {
        const int sym0 = sm->seq_s[0];
        if (wid == 2) {
            float a = g_pgt[sym0 * 64 + lane] * sm->trace_state[0][lane]
                    + g_pgt[sym0 * 64 + 32 + lane] * sm->trace_state[0][lane + 32];
            #pragma unroll
            for (int o = 16; o > 0; o >>= 1) a += __shfl_xor_sync(0xffffffffu, a, o);
            if (lane == 0) sm->scal[0] = 1.f / (1.f + __expf(-a));
        } else if (wid == 3) {
            float a = g_ppt[sym0 * 64 + lane] * sm->trace_state[0][lane]
                    + g_ppt[sym0 * 64 + 32 + lane] * sm->trace_state[0][lane + 32];
            #pragma unroll
            for (int o = 16; o > 0; o >>= 1) a += __shfl_xor_sync(0xffffffffu, a, o);
            if (lane == 0) sm->scal[1] = 1.f / (1.f + __expf(-a));
        } else if (wid >= 6 && wid < 10) {
            const int d  = (wid - 6) * 16 + (lane & 15);
            const int sb = (lane >> 4) * 32;
            float acc = 0.f;
            #pragma unroll 8
            for (int j = 0; j < 32; j++)
                acc += sm->trace_state[0][sb + j] * g_pvt[sym0 * 4096 + (sb + j) * 64 + d];
            acc += __shfl_xor_sync(0xffffffffu, acc, 16);
            if ((lane >> 4) == 0) sm->pv2[0][d] = tanh_fast(acc);
        }
        __syncthreads();
    }

    asm volatile("barrier.cluster.arrive.aligned;" ::: "memory");
    asm volatile("barrier.cluster.wait.aligned;" ::: "memory");

    const unsigned int flags_u = s2u(&sm->flags[0]);
    const unsigned int pvst_u  = s2u(&sm->pvst[0]);
    const unsigned int gst_u   = s2u(&sm->gst[0]);

    if (rank == 0) {
        // ===================== recurrence CTA =====================
        int cb = 0;

        for (int t = 0; t < TLEN_; t++) {
            const int sym  = sm->seq_s[t];
            const int sym1 = sm->seq_s[t + 1];
            const int bp   = t & 1;

            if (tid == 0) st_rel_flag(flags_u + 4u * t, 1);   // publish step t

            // ---- cp.async preloads for the F region (operands depend only on sym1)
            if (wid == 6) {
                if (lane < 16)
                    cp_async16(gst_u + (unsigned)lane * 16u,
                               (const char*)(g_pgt + sym1 * 64) + lane * 16);
                cp_commit();
            } else if (wid == 7) {
                if (lane < 16)
                    cp_async16(gst_u + 256u + (unsigned)lane * 16u,
                               (const char*)(g_ppt + sym1 * 64) + lane * 16);
                cp_commit();
            } else if (wid >= 8 && wid < 12) {
                const int idx = (wid - 8) * 32 + lane;
                const char* base = (const char*)(g_pvh + (size_t)sym1 * 4096);
                #pragma unroll
                for (int c = 0; c < 4; c++)
                    cp_async16(pvst_u + (unsigned)(idx + c * 128) * 16u,
                               base + (size_t)(idx + c * 128) * 16);
                cp_commit();
            }

            // ---- A: pointer update in registers (all warps, redundant)
            const float pushs = sm->scal[0];
            const float pops  = sm->scal[1];
            const int i0 = lane * 2;
            float p0 = sm->pb[bp][i0], p1 = sm->pb[bp][i0 + 1];
            float dd = __shfl_down_sync(0xffffffffu, p0, 1);
            if (lane == 31) dd = 0.f;
            if (pops > THR_) {
                p0 = pops * p1 + (1.f - pops) * p0;
                p1 = pops * dd + (1.f - pops) * p1;
            }
            float uu = __shfl_up_sync(0xffffffffu, p1, 1);
            if (lane == 0) uu = 0.f;
            const float q0 = pushs * uu + (1.f - pushs) * p0;
            const float q1 = pushs * p0 + (1.f - pushs) * p1;
            const bool push = pushs > THR_;
            const float m0 = push ? q0 * (1.f - q0) : p0;
            const float m1 = push ? q1 * (1.f - q1) : p1;
            float cp = push ? (q0 * q0 + q1 * q1) : 0.f;
            #pragma unroll
            for (int o = 16; o > 0; o >>= 1) cp += __shfl_xor_sync(0xffffffffu, cp, o);
            if (wid == 31) {
                sm->pb[bp ^ 1][i0]     = push ? q0 : p0;
                sm->pb[bp ^ 1][i0 + 1] = push ? q1 : p1;
            }

            // ---- B: phase-2 T contraction (R10 form)
            {
                const int r0 = wid * 2, r1 = r0 + 1;
                float fa[8], fb[8];
                contract2((const uint4*)(g_Th + (size_t)(r0 * I_ + sym) * 4096),
                          (const uint4*)(g_Th + (size_t)(r1 * I_ + sym) * 4096),
                          sm->trace_top[t], lane, fa, fb);
                const float s0 = sm->trace_state[t][r0];
                const float s1 = sm->trace_state[t][r1];
                if (lr == 0) {
                    float4 w;
                    w.x = s0 * fa[0] + s1 * fb[0]; w.y = s0 * fa[1] + s1 * fb[1];
                    w.z = s0 * fa[2] + s1 * fb[2]; w.w = s0 * fa[3] + s1 * fb[3];
                    *(float4*)&sm->part[wid * 64 + lc * 8] = w;
                    w.x = s0 * fa[4] + s1 * fb[4]; w.y = s0 * fa[5] + s1 * fb[5];
                    w.z = s0 * fa[6] + s1 * fb[6]; w.w = s0 * fa[7] + s1 * fb[7];
                    *(float4*)&sm->part[wid * 64 + lc * 8 + 4] = w;
                }
            }
            __syncthreads();   // B1

            // ---- D: reduce || stack_top(t+1) || content update
            //      F (gates+pushv) released by a NAMED barrier on warps {0,1,6..11}
            //      so it overlaps D's stragglers instead of waiting for them.
            if (tid < 64) {
                float ns = 0.f;
                #pragma unroll
                for (int r = 0; r < 32; r++) ns += sm->part[r * 64 + tid];
                sm->trace_state[t + 1][tid] = ns;
                sm->sh[tid] = __float2half(ns);
            } else if (wid >= 2 && wid < 6) {
                const int d  = (wid - 2) * 16 + (lane & 15);
                const int kb = (lane >> 4) * 32;
                float acc = 0.f;
                #pragma unroll 8
                for (int j = 0; j < 32; j++) {
                    float mv = __shfl_sync(0xffffffffu, (j & 1) ? m1 : m0,
                                           (kb >> 1) + (j >> 1));
                    acc += mv * sm->content[cb][(kb + j) * 64 + d];
                }
                acc += __shfl_xor_sync(0xffffffffu, acc, 16);
                if ((lane >> 4) == 0) {
                    __half2 h = __float2half2_rn(acc + cp * sm->pv2[bp][d]);
                    sm->trace_top[t + 1][d] = *(unsigned int*)&h;
                }
            } else if (wid >= 16) {
                if (push) {
                    const int tidc = tid - 512;
                    const int kbase = tidc >> 6;      // warp-uniform
                    const float pvd = sm->pv2[bp][tidc & 63];
                    #pragma unroll
                    for (int i = 0; i < 8; i++) {
                        const int k = kbase + 8 * i;
                        float wk = __shfl_sync(0xffffffffu, (k & 1) ? q1 : q0, k >> 1);
                        const int e = tidc + 512 * i;
                        sm->content[cb ^ 1][e] =
                            sm->content[cb][e] * (1.f - wk) + pvd * wk;
                    }
                }
            }

            // ---- F: gates(t+1) + pushv(t+1), gated only on the reduce (named bar)
            if (wid < 2 || (wid >= 6 && wid < 12)) {
                asm volatile("bar.sync 4, 256;" ::: "memory");   // {0,1,6..11}
                if (wid == 6) {
                    cp_wait0();
                    float a = sm->gst[lane] * sm->trace_state[t + 1][lane]
                            + sm->gst[lane + 32] * sm->trace_state[t + 1][lane + 32];
                    #pragma unroll
                    for (int o = 16; o > 0; o >>= 1) a += __shfl_xor_sync(0xffffffffu, a, o);
                    if (lane == 0) sm->scal[0] = 1.f / (1.f + __expf(-a));
                } else if (wid == 7) {
                    cp_wait0();
                    float a = sm->gst[64 + lane] * sm->trace_state[t + 1][lane]
                            + sm->gst[64 + lane + 32] * sm->trace_state[t + 1][lane + 32];
                    #pragma unroll
                    for (int o = 16; o > 0; o >>= 1) a += __shfl_xor_sync(0xffffffffu, a, o);
                    if (lane == 0) sm->scal[1] = 1.f / (1.f + __expf(-a));
                } else if (wid >= 8) {
                    cp_wait0();
                    const int d   = (wid - 8) * 16 + (lane >> 1);
                    const int shh = lane & 1;
                    const uint4* pr = (const uint4*)(sm->pvst + d * 64 + shh * 32);
                    const __half2* s2h = (const __half2*)sm->sh + shh * 16;
                    float a = 0.f;
                    #pragma unroll
                    for (int u = 0; u < 4; u++) {
                        uint4 v = pr[u];
                        __half2 h0 = __hmul2(s2h[u * 4 + 0], *(__half2*)&v.x);
                        __half2 h1 = __hmul2(s2h[u * 4 + 1], *(__half2*)&v.y);
                        __half2 h2 = __hmul2(s2h[u * 4 + 2], *(__half2*)&v.z);
                        __half2 h3 = __hmul2(s2h[u * 4 + 3], *(__half2*)&v.w);
                        float2 f0 = __half22float2(h0), f1 = __half22float2(h1);
                        float2 f2 = __half22float2(h2), f3 = __half22float2(h3);
                        a += (f0.x + f0.y) + (f1.x + f1.y) + (f2.x + f2.y) + (f3.x + f3.y);
                    }
                    a += __shfl_xor_sync(0xffffffffu, a, 1);
                    sm->pv2[bp ^ 1][d] = tanh_fast(a);
                }
            }
            if (push) cb ^= 1;
            __syncthreads();   // B3 / loop top
        }
    } else {
        // ===================== output CTA (lagging consumer) =====================
        const int r0 = wid * 2, r1 = r0 + 1;
        const unsigned int peer = 0u;

        for (int t = 0; t < TLEN_; t++) {
            if (tid == 0) {
                while (ld_acq_remote(flags_u + 4u * t, peer) == 0) { }
            }
            __syncthreads();
            if (tid < 64) {
                unsigned int v = ld_remote_u32(s2u(&sm->trace_state[t][tid]), peer);
                sm->tstate_l[tid] = __uint_as_float(v);
            } else if (tid < 128) {
                sm->ttop_l[tid - 64] = ld_remote_u32(s2u(&sm->trace_top[t][tid - 64]), peer);
            }
            __syncthreads();

            const int sym = sm->seq_s[t];
            float fa[8], fb[8];
            contract2((const uint4*)(g_Oh + (size_t)(r0 * I_ + sym) * 4096),
                      (const uint4*)(g_Oh + (size_t)(r1 * I_ + sym) * 4096),
                      sm->ttop_l, lane, fa, fb);
            const float s0 = sm->tstate_l[r0];
            const float s1 = sm->tstate_l[r1];
            if (lr == 0) {
                float4 w;
                w.x = s0 * fa[0] + s1 * fb[0]; w.y = s0 * fa[1] + s1 * fb[1];
                w.z = s0 * fa[2] + s1 * fb[2]; w.w = s0 * fa[3] + s1 * fb[3];
                *(float4*)&sm->part[wid * 64 + lc * 8] = w;
                w.x = s0 * fa[4] + s1 * fb[4]; w.y = s0 * fa[5] + s1 * fb[5];
                w.z = s0 * fa[6] + s1 * fb[6]; w.w = s0 * fa[7] + s1 * fb[7];
                *(float4*)&sm->part[wid * 64 + lc * 8 + 4] = w;
            }
            __syncthreads();

            if (tid < 64) {
                float m = 0.f;
                #pragma unroll
                for (int r = 0; r < 32; r++) m += sm->part[r * 64 + tid];
                out[((size_t)b * TLEN_ + t) * NO_ + tid] = m;
            }
        }
    }

    asm volatile("barrier.cluster.arrive.aligned;" ::: "memory");
    asm volatile("barrier.cluster.wait.aligned;" ::: "memory");
}

extern "C" void kernel_launch(void* const* d_in, const int* in_sizes, int n_in,
                              void* d_out, int out_size)
{
    const int*   seq   = (const int*)  d_in[0];
    const float* Tt    = (const float*)d_in[1];
    const float* Ot    = (const float*)d_in[2];
    const float* pgate = (const float*)d_in[3];
    const float* pop   = (const float*)d_in[4];
    const float* pval  = (const float*)d_in[5];
    const float* initl = (const float*)d_in[6];
    float* out = (float*)d_out;

    cudaFuncSetAttribute(fpt_kernel, cudaFuncAttributeMaxDynamicSharedMemorySize,
                         (int)sizeof(Smem));

    cvt_kernel<<<(unsigned)((TOTAL4 + 255) / 256), 256>>>(Tt, Ot);
    tr_kernel<<<(I_ * S_ * D_ + 255) / 256, 256>>>(pgate, pop, pval);
    fpt_kernel<<<2 * B_, NTHREADS, sizeof(Smem)>>>(seq, initl, out);
}